// round 8
// baseline (speedup 1.0000x reference)
#include <cuda_runtime.h>
#include <cuda_bf16.h>
#include <cstdint>

// Flatten 2x2 blocks:
//   out[bc, i*1024 + 4j + 2r + s] = x[bc, 2i+r, 2j+s]
// x: (32, 3, 512, 512) fp32. bc in [0,96), i in [0,256), j in [0,256).
//
// R8: persistent single-wave grid. R7 showed bench time = DRAM floor +
// wave-structure term (3072 fat CTAs beat 12288 small ones by 0.45us).
// Endpoint: 296 CTAs (148 SMs x 2) of 1024 threads, one wave, each CTA
// grid-striding over the 3072 strips (8 i-values / 32 KB in / 32 KB out
// per strip). At any instant the active strips form one contiguous band,
// preserving burst locality. Coalescing identical to R7: float2x4 loads
// front-batched, 2x STG.128 per thread per strip.

static constexpr unsigned NUM_STRIPS = 3072u;   // 96 bc * 32 strips
static constexpr unsigned GRID = 296u;          // 148 SMs * 2 CTAs

__global__ __launch_bounds__(1024)
void flatten2x2_kernel(const float2* __restrict__ x2, float4* __restrict__ out4) {
    unsigned tid = threadIdx.x;           // 0..1023
    unsigned j   = tid & 255u;            // column-pair index
    unsigned di  = tid >> 8;              // 0..3: i-pair slot within strip

    for (unsigned s = blockIdx.x; s < NUM_STRIPS; s += GRID) {
        unsigned bc = s >> 5;                       // 0..95
        unsigned i0 = (s & 31u) * 8u + 2u * di;     // base i (this thread: i0, i0+1)

        // input: float2 units, row stride 256, image stride 131072
        const float2* base = x2 + (size_t)bc * 131072u + (size_t)(2u * i0) * 256u + j;
        float2 a0 = __ldg(base);            // row 2*i0
        float2 b0 = __ldg(base + 256u);     // row 2*i0+1
        float2 a1 = __ldg(base + 512u);     // row 2*i0+2
        float2 b1 = __ldg(base + 768u);     // row 2*i0+3

        // output: float4 units, i stride 256, image stride 65536
        float4* obase = out4 + (size_t)bc * 65536u + (size_t)i0 * 256u + j;
        obase[0]    = make_float4(a0.x, a0.y, b0.x, b0.y);   // i = i0
        obase[256u] = make_float4(a1.x, a1.y, b1.x, b1.y);   // i = i0+1
    }
}

extern "C" void kernel_launch(void* const* d_in, const int* in_sizes, int n_in,
                              void* d_out, int out_size) {
    const float2* x2 = (const float2*)d_in[0];
    float4* out4 = (float4*)d_out;

    flatten2x2_kernel<<<GRID, 1024>>>(x2, out4);
}

// round 9
// speedup vs baseline: 1.0312x; 1.0312x over previous
#include <cuda_runtime.h>
#include <cuda_bf16.h>
#include <cstdint>

// Flatten 2x2 blocks:
//   out[bc, i*1024 + 4j + 2r + s] = x[bc, 2i+r, 2j+s]
// x: (32, 3, 512, 512) fp32. bc in [0,96), i in [0,256), j in [0,256).
//
// R9: geometry interpolation. R6(12288x256)=35.30, R7(3072x1024)=34.85,
// R8(persistent,looped)=36.99 -> winning axis is fatter STRAIGHT-LINE
// CTAs, not loops. Here: 1536 CTAs x 1024 threads; each CTA owns a
// contiguous 64 KB input / 64 KB output strip (16 i-values); each thread
// straight-lines 4 i-values with 8 front-batched float2 loads (MLP=8)
// then 4 coalesced STG.128. ~5 waves.

__global__ __launch_bounds__(1024)
void flatten2x2_kernel(const float2* __restrict__ x2, float4* __restrict__ out4) {
    unsigned tid = threadIdx.x;           // 0..1023
    unsigned j   = tid & 255u;            // column-pair index
    unsigned di  = tid >> 8;              // 0..3: slot within strip
    unsigned blk = blockIdx.x;            // 0..1535
    unsigned bc  = blk >> 4;              // 0..95
    // strip covers i in [16*(blk&15), +16); this thread: i0, i0+1, i0+8, i0+9
    unsigned i0  = (blk & 15u) * 16u + 2u * di;

    // input: float2 units, row stride 256, image stride 131072
    const float2* base = x2 + (size_t)bc * 131072u + (size_t)(2u * i0) * 256u + j;
    // first pair: i0, i0+1  (rows 2*i0 .. 2*i0+3)
    float2 a0 = __ldg(base);
    float2 b0 = __ldg(base + 256u);
    float2 a1 = __ldg(base + 512u);
    float2 b1 = __ldg(base + 768u);
    // second pair: i0+8, i0+9 (rows 2*i0+16 .. 2*i0+19) -> +16*256 float2
    float2 a2 = __ldg(base + 4096u);
    float2 b2 = __ldg(base + 4096u + 256u);
    float2 a3 = __ldg(base + 4096u + 512u);
    float2 b3 = __ldg(base + 4096u + 768u);

    // output: float4 units, i stride 256, image stride 65536
    float4* obase = out4 + (size_t)bc * 65536u + (size_t)i0 * 256u + j;
    obase[0]            = make_float4(a0.x, a0.y, b0.x, b0.y);  // i = i0
    obase[256u]         = make_float4(a1.x, a1.y, b1.x, b1.y);  // i = i0+1
    obase[8u * 256u]    = make_float4(a2.x, a2.y, b2.x, b2.y);  // i = i0+8
    obase[9u * 256u]    = make_float4(a3.x, a3.y, b3.x, b3.y);  // i = i0+9
}

extern "C" void kernel_launch(void* const* d_in, const int* in_sizes, int n_in,
                              void* d_out, int out_size) {
    const float2* x2 = (const float2*)d_in[0];
    float4* out4 = (float4*)d_out;

    // 96 images x 16 strips (16 i-values each) = 1536 CTAs, 1024 threads
    flatten2x2_kernel<<<1536, 1024>>>(x2, out4);
}

// round 10
// speedup vs baseline: 1.1115x; 1.0779x over previous
#include <cuda_runtime.h>
#include <cuda_bf16.h>
#include <cstdint>

// Flatten 2x2 blocks:
//   out[bc, i*1024 + 4j + 2r + s] = x[bc, 2i+r, 2j+s]
// x: (32, 3, 512, 512) fp32. bc in [0,96), i in [0,256), j in [0,256).
//
// R10 (= R7 verbatim, confirmation run): measured geometry optimum.
// Sweep: 24576x256=35.30, 12288x256=35.30, 6144x256=35.55, 3072x1024=34.85,
// 1536x1024=35.87, persistent-296=36.99. The task is pinned at the
// sustained mixed-R/W DRAM floor (201 MB compulsory/replay); only launch
// geometry moves the residual. 3072 CTAs x 1024 threads, each CTA owns a
// contiguous 32 KB in / 32 KB out strip (8 i-values), straight-line body:
// 4 front-batched coalesced float2 loads + 2 coalesced STG.128 per thread.

__global__ __launch_bounds__(1024)
void flatten2x2_kernel(const float2* __restrict__ x2, float4* __restrict__ out4) {
    unsigned tid = threadIdx.x;                 // 0..1023
    unsigned j   = tid & 255u;                  // column-pair index
    unsigned di  = tid >> 8;                    // 0..3: i-pair slot within strip
    unsigned blk = blockIdx.x;                  // 0..3071
    unsigned i0  = (blk & 31u) * 8u + 2u * di;  // this thread: i = i0, i0+1
    unsigned bc  = blk >> 5;                    // 0..95

    // input: float2 units, row stride 256, image stride 131072
    const float2* base = x2 + (size_t)bc * 131072u + (size_t)(2u * i0) * 256u + j;
    float2 a0 = __ldg(base);            // row 2*i0
    float2 b0 = __ldg(base + 256u);     // row 2*i0+1
    float2 a1 = __ldg(base + 512u);     // row 2*i0+2
    float2 b1 = __ldg(base + 768u);     // row 2*i0+3

    // output: float4 units, i stride 256, image stride 65536
    float4* obase = out4 + (size_t)bc * 65536u + (size_t)i0 * 256u + j;
    obase[0]    = make_float4(a0.x, a0.y, b0.x, b0.y);   // i = i0
    obase[256u] = make_float4(a1.x, a1.y, b1.x, b1.y);   // i = i0+1
}

extern "C" void kernel_launch(void* const* d_in, const int* in_sizes, int n_in,
                              void* d_out, int out_size) {
    const float2* x2 = (const float2*)d_in[0];
    float4* out4 = (float4*)d_out;

    // 96 images x 32 strips (8 i-values each) = 3072 CTAs, 1024 threads
    flatten2x2_kernel<<<3072, 1024>>>(x2, out4);
}